// round 4
// baseline (speedup 1.0000x reference)
#include <cuda_runtime.h>

#define D 128
#define NMAX 100000

// Scratch m1[N][128]: residual + SpMM accumulator, then dropout in-place.
__device__ float g_m1[(size_t)NMAX * D];

// ---------------------------------------------------------------------------
// JAX threefry2x32 with key = (0, 42)
// Confirmed convention (round-3 probe): ctr = (hi=0, lo=i), bits = x0.
// ---------------------------------------------------------------------------
__device__ __forceinline__ unsigned int threefry_x0_k42(unsigned int ctr_lo) {
    unsigned int x0 = 0u;
    unsigned int x1 = ctr_lo;
    const unsigned int ks0 = 0u;
    const unsigned int ks1 = 42u;
    const unsigned int ks2 = 0u ^ 42u ^ 0x1BD11BDAu;
    x0 += ks0; x1 += ks1;
#define TF_ROUND(r) { x0 += x1; x1 = __funnelshift_l(x1, x1, (r)); x1 ^= x0; }
    TF_ROUND(13) TF_ROUND(15) TF_ROUND(26) TF_ROUND(6)
    x0 += ks1; x1 += ks2 + 1u;
    TF_ROUND(17) TF_ROUND(29) TF_ROUND(16) TF_ROUND(24)
    x0 += ks2; x1 += ks0 + 2u;
    TF_ROUND(13) TF_ROUND(15) TF_ROUND(26) TF_ROUND(6)
    x0 += ks0; x1 += ks1 + 3u;
    TF_ROUND(17) TF_ROUND(29) TF_ROUND(16) TF_ROUND(24)
    x0 += ks1; x1 += ks2 + 4u;
    TF_ROUND(13) TF_ROUND(15) TF_ROUND(26) TF_ROUND(6)
    x0 += ks2;  // x1 not needed
#undef TF_ROUND
    return x0;
}

__device__ __forceinline__ float drop_one(float v, unsigned int i) {
    unsigned int bits = threefry_x0_k42(i);
    float u = __uint_as_float(0x3f800000u | (bits >> 9)) - 1.0f;
    return (u < 0.9f) ? (v * (1.0f / 0.9f)) : 0.0f;
}

// ---------------------------------------------------------------------------
// Kernel 1: m1 = e = embed_w[x];  out[:, 0:128] = e
// ---------------------------------------------------------------------------
__global__ void init_kernel(const int* __restrict__ x,
                            const float* __restrict__ embed_w,
                            float* __restrict__ out, int N) {
    int idx = blockIdx.x * blockDim.x + threadIdx.x;   // over N*32 float4s
    int total = N * 32;
    if (idx >= total) return;
    int r  = idx >> 5;
    int c4 = idx & 31;
    int src = x[r];
    float4 v = reinterpret_cast<const float4*>(embed_w)[(size_t)src * 32 + c4];
    reinterpret_cast<float4*>(g_m1)[(size_t)r * 32 + c4] = v;
    reinterpret_cast<float4*>(out)[(size_t)r * 64 + c4] = v;   // first half of [N,256]
}

// ---------------------------------------------------------------------------
// Kernel 2: COO SpMM via atomics: m1[row] += val * e[col]
// ---------------------------------------------------------------------------
__global__ void spmm_kernel(const int* __restrict__ row,
                            const int* __restrict__ col,
                            const float* __restrict__ vals,
                            const int* __restrict__ x,
                            const float* __restrict__ embed_w, int E) {
    __shared__ int   s_row[64];
    __shared__ int   s_src[64];
    __shared__ float s_val[64];
    int base = blockIdx.x * 64;
    int t = threadIdx.x;
    if (t < 64) {
        int e = base + t;
        if (e < E) {
            s_row[t] = row[e];
            s_val[t] = vals[e];
            s_src[t] = x[col[e]];
        } else {
            s_row[t] = -1;
        }
    }
    __syncthreads();
    int warp = t >> 5;
    int lane = t & 31;
#pragma unroll
    for (int j = 0; j < 8; j++) {
        int li = warp * 8 + j;
        int r = s_row[li];
        if (r < 0) continue;
        float v  = s_val[li];
        int src  = s_src[li];
        float4 ev = *reinterpret_cast<const float4*>(embed_w + (size_t)src * D + lane * 4);
        float* dst = g_m1 + (size_t)r * D + lane * 4;
        atomicAdd(dst + 0, ev.x * v);
        atomicAdd(dst + 1, ev.y * v);
        atomicAdd(dst + 2, ev.z * v);
        atomicAdd(dst + 3, ev.w * v);
    }
}

// ---------------------------------------------------------------------------
// Kernel 3: in-place dropout; ctr=(0,i), bits=x0 (confirmed). 4 elems/thread.
// ---------------------------------------------------------------------------
__global__ void dropout_kernel(int total4) {
    int q = blockIdx.x * blockDim.x + threadIdx.x;   // float4 index
    if (q >= total4) return;
    unsigned int i0 = (unsigned int)q * 4u;
    float4 v = reinterpret_cast<float4*>(g_m1)[q];
    v.x = drop_one(v.x, i0 + 0u);
    v.y = drop_one(v.y, i0 + 1u);
    v.z = drop_one(v.z, i0 + 2u);
    v.w = drop_one(v.w, i0 + 3u);
    reinterpret_cast<float4*>(g_m1)[q] = v;
}

// ---------------------------------------------------------------------------
// Kernel 4: x1 = leaky_relu(m1 @ W^T + b); out[:, 128:256] = x1
// ---------------------------------------------------------------------------
__global__ __launch_bounds__(256, 2)
void gemm_kernel(const float* __restrict__ W,
                 const float* __restrict__ bias,
                 float* __restrict__ out, int N) {
    __shared__ float As[128 * 33];   // [row][k] padded
    __shared__ float Ws[128 * 33];   // [outcol][k] padded
    const int t  = threadIdx.x;
    const int tx = t & 15;           // out-col group
    const int ty = t >> 4;           // row group
    const int brow = blockIdx.x * 128;

    float acc[8][8];
#pragma unroll
    for (int u = 0; u < 8; u++)
#pragma unroll
        for (int v = 0; v < 8; v++) acc[u][v] = 0.0f;

#pragma unroll 1
    for (int kk = 0; kk < 4; kk++) {
        if (kk) __syncthreads();
#pragma unroll
        for (int i = 0; i < 4; i++) {
            int idx = t + i * 256;       // 1024 float4 loads: 128 rows x 8 float4
            int r   = idx >> 3;
            int c4  = (idx & 7) * 4;
            int gr  = brow + r;
            float4 av = make_float4(0.f, 0.f, 0.f, 0.f);
            if (gr < N)
                av = *reinterpret_cast<const float4*>(g_m1 + (size_t)gr * D + kk * 32 + c4);
            As[r * 33 + c4 + 0] = av.x;
            As[r * 33 + c4 + 1] = av.y;
            As[r * 33 + c4 + 2] = av.z;
            As[r * 33 + c4 + 3] = av.w;
            float4 wv = *reinterpret_cast<const float4*>(W + (size_t)r * D + kk * 32 + c4);
            Ws[r * 33 + c4 + 0] = wv.x;
            Ws[r * 33 + c4 + 1] = wv.y;
            Ws[r * 33 + c4 + 2] = wv.z;
            Ws[r * 33 + c4 + 3] = wv.w;
        }
        __syncthreads();
#pragma unroll 8
        for (int k = 0; k < 32; k++) {
            float a[8], w[8];
#pragma unroll
            for (int u = 0; u < 8; u++) a[u] = As[(ty + 16 * u) * 33 + k];
#pragma unroll
            for (int v = 0; v < 8; v++) w[v] = Ws[(tx + 16 * v) * 33 + k];
#pragma unroll
            for (int u = 0; u < 8; u++)
#pragma unroll
                for (int v = 0; v < 8; v++) acc[u][v] += a[u] * w[v];
        }
    }

    float bv[8];
#pragma unroll
    for (int v = 0; v < 8; v++) bv[v] = bias[tx + 16 * v];

#pragma unroll
    for (int u = 0; u < 8; u++) {
        int gr = brow + ty + 16 * u;
        if (gr >= N) continue;
        float* o = out + (size_t)gr * 256 + 128;
#pragma unroll
        for (int v = 0; v < 8; v++) {
            float y = acc[u][v] + bv[v];
            y = (y >= 0.0f) ? y : 0.2f * y;
            o[tx + 16 * v] = y;
        }
    }
}

// ---------------------------------------------------------------------------
extern "C" void kernel_launch(void* const* d_in, const int* in_sizes, int n_in,
                              void* d_out, int out_size) {
    const int*   x       = (const int*)d_in[0];
    const int*   row     = (const int*)d_in[1];
    const int*   col     = (const int*)d_in[2];
    const float* vals    = (const float*)d_in[3];
    const float* embed_w = (const float*)d_in[4];
    const float* fc_w    = (const float*)d_in[5];
    const float* fc_b    = (const float*)d_in[6];
    float* out = (float*)d_out;

    const int N = in_sizes[0];
    const int E = in_sizes[1];

    // 1) m1 = e, out[:, :128] = e
    {
        int total = N * 32;
        init_kernel<<<(total + 255) / 256, 256>>>(x, embed_w, out, N);
    }
    // 2) SpMM atomics into m1
    {
        int blocks = (E + 63) / 64;
        spmm_kernel<<<blocks, 256>>>(row, col, vals, x, embed_w, E);
    }
    // 3) dropout in-place (confirmed: ctr=(0,i), bits=x0)
    {
        int total4 = (N * D) / 4;
        dropout_kernel<<<(total4 + 255) / 256, 256>>>(total4);
    }
    // 4) FC + leaky relu -> out[:, 128:]
    {
        int blocks = (N + 127) / 128;
        gemm_kernel<<<blocks, 256>>>(fc_w, fc_b, out, N);
    }
}

// round 5
// speedup vs baseline: 2.0706x; 2.0706x over previous
#include <cuda_runtime.h>

#define D 128
#define NMAX 100000
#define EMAX 3200000

// Scratch: m1[N][128], CSR build arrays.
__device__ float g_m1[(size_t)NMAX * D];
__device__ int   g_counts[NMAX];
__device__ int   g_row_start[NMAX + 1];
__device__ int   g_cursor[NMAX];
__device__ int   g_scol[EMAX];    // sorted source-node index (x[col[e]])
__device__ float g_sval[EMAX];    // sorted edge value

// ---------------------------------------------------------------------------
// JAX threefry2x32, key=(0,42); confirmed: ctr=(hi=0, lo=i), bits = x0.
// ---------------------------------------------------------------------------
__device__ __forceinline__ unsigned int threefry_x0_k42(unsigned int ctr_lo) {
    unsigned int x0 = 0u;
    unsigned int x1 = ctr_lo;
    const unsigned int ks1 = 42u;
    const unsigned int ks2 = 42u ^ 0x1BD11BDAu;
    x1 += ks1;
#define TF_ROUND(r) { x0 += x1; x1 = __funnelshift_l(x1, x1, (r)); x1 ^= x0; }
    TF_ROUND(13) TF_ROUND(15) TF_ROUND(26) TF_ROUND(6)
    x0 += ks1; x1 += ks2 + 1u;
    TF_ROUND(17) TF_ROUND(29) TF_ROUND(16) TF_ROUND(24)
    x0 += ks2; x1 += 0u + 2u;
    TF_ROUND(13) TF_ROUND(15) TF_ROUND(26) TF_ROUND(6)
    x0 += 0u;  x1 += ks1 + 3u;
    TF_ROUND(17) TF_ROUND(29) TF_ROUND(16) TF_ROUND(24)
    x0 += ks1; x1 += ks2 + 4u;
    TF_ROUND(13) TF_ROUND(15) TF_ROUND(26) TF_ROUND(6)
    x0 += ks2;
#undef TF_ROUND
    return x0;
}

__device__ __forceinline__ float drop_one(float v, unsigned int i) {
    unsigned int bits = threefry_x0_k42(i);
    float u = __uint_as_float(0x3f800000u | (bits >> 9)) - 1.0f;
    return (u < 0.9f) ? (v * (1.0f / 0.9f)) : 0.0f;
}

// ---------------------------------------------------------------------------
// Kernel 1: out[:, 0:128] = e = embed_w[x]
// ---------------------------------------------------------------------------
__global__ void copy_e_kernel(const int* __restrict__ x,
                              const float* __restrict__ embed_w,
                              float* __restrict__ out, int N) {
    int idx = blockIdx.x * blockDim.x + threadIdx.x;   // over N*32 float4s
    if (idx >= N * 32) return;
    int r  = idx >> 5;
    int c4 = idx & 31;
    int src = x[r];
    float4 v = reinterpret_cast<const float4*>(embed_w)[(size_t)src * 32 + c4];
    reinterpret_cast<float4*>(out)[(size_t)r * 64 + c4] = v;
}

// ---------------------------------------------------------------------------
// CSR build: zero counts -> histogram -> scan -> scatter
// ---------------------------------------------------------------------------
__global__ void zero_counts_kernel(int N) {
    int i = blockIdx.x * blockDim.x + threadIdx.x;
    if (i < N) g_counts[i] = 0;
}

__global__ void hist_kernel(const int* __restrict__ row, int E) {
    int e = blockIdx.x * blockDim.x + threadIdx.x;
    if (e < E) atomicAdd(&g_counts[row[e]], 1);
}

__global__ void scan_kernel(int N, int E) {
    __shared__ int sums[1024];
    int t = threadIdx.x;
    const int chunk = (N + 1023) / 1024;
    int lo = t * chunk;
    int hi = min(lo + chunk, N);
    int s = 0;
    for (int b = lo; b < hi; b++) s += g_counts[b];
    sums[t] = s;
    __syncthreads();
    // inclusive Hillis-Steele scan over 1024 partials
    for (int off = 1; off < 1024; off <<= 1) {
        int v = (t >= off) ? sums[t - off] : 0;
        __syncthreads();
        sums[t] += v;
        __syncthreads();
    }
    int prefix = (t == 0) ? 0 : sums[t - 1];
    for (int b = lo; b < hi; b++) {
        g_row_start[b] = prefix;
        g_cursor[b]    = prefix;
        prefix += g_counts[b];
    }
    if (t == 1023) g_row_start[N] = E;
}

__global__ void scatter_kernel(const int* __restrict__ row,
                               const int* __restrict__ col,
                               const float* __restrict__ vals,
                               const int* __restrict__ x, int E) {
    int e = blockIdx.x * blockDim.x + threadIdx.x;
    if (e >= E) return;
    int r = row[e];
    int pos = atomicAdd(&g_cursor[r], 1);
    g_scol[pos] = x[col[e]];
    g_sval[pos] = vals[e];
}

// ---------------------------------------------------------------------------
// Fused CSR SpMM + residual + dropout:
// m1[r] = dropout( e[r] + sum_j val_j * embed_w[colsrc_j] )
// One warp per row; each lane owns a float4 of the 128-wide row.
// ---------------------------------------------------------------------------
__global__ __launch_bounds__(256)
void spmm_csr_kernel(const int* __restrict__ x,
                     const float* __restrict__ embed_w, int N) {
    int warp = (blockIdx.x * blockDim.x + threadIdx.x) >> 5;
    if (warp >= N) return;
    int lane = threadIdx.x & 31;
    int r = warp;

    const float4* ew4 = reinterpret_cast<const float4*>(embed_w);

    // residual e[r]
    float4 acc = ew4[(size_t)x[r] * 32 + lane];

    int start = g_row_start[r];
    int end   = g_row_start[r + 1];

    for (int base = start; base < end; base += 32) {
        int j = base + lane;
        int  c = 0;
        float v = 0.0f;
        if (j < end) { c = g_scol[j]; v = g_sval[j]; }
        int m = min(32, end - base);
#pragma unroll 4
        for (int k = 0; k < m; k++) {
            int   ck = __shfl_sync(0xFFFFFFFFu, c, k);
            float vk = __shfl_sync(0xFFFFFFFFu, v, k);
            float4 ev = ew4[(size_t)ck * 32 + lane];
            acc.x += vk * ev.x;
            acc.y += vk * ev.y;
            acc.z += vk * ev.z;
            acc.w += vk * ev.w;
        }
    }

    // fused dropout (row-major element index)
    unsigned int i0 = (unsigned int)r * 128u + (unsigned int)lane * 4u;
    acc.x = drop_one(acc.x, i0 + 0u);
    acc.y = drop_one(acc.y, i0 + 1u);
    acc.z = drop_one(acc.z, i0 + 2u);
    acc.w = drop_one(acc.w, i0 + 3u);

    reinterpret_cast<float4*>(g_m1)[(size_t)r * 32 + lane] = acc;
}

// ---------------------------------------------------------------------------
// Kernel 4: x1 = leaky_relu(m1 @ W^T + b); out[:, 128:256] = x1
// ---------------------------------------------------------------------------
__global__ __launch_bounds__(256, 2)
void gemm_kernel(const float* __restrict__ W,
                 const float* __restrict__ bias,
                 float* __restrict__ out, int N) {
    __shared__ float As[128 * 33];   // [row][k] padded
    __shared__ float Ws[128 * 33];   // [outcol][k] padded
    const int t  = threadIdx.x;
    const int tx = t & 15;           // out-col group
    const int ty = t >> 4;           // row group
    const int brow = blockIdx.x * 128;

    float acc[8][8];
#pragma unroll
    for (int u = 0; u < 8; u++)
#pragma unroll
        for (int v = 0; v < 8; v++) acc[u][v] = 0.0f;

#pragma unroll 1
    for (int kk = 0; kk < 4; kk++) {
        if (kk) __syncthreads();
#pragma unroll
        for (int i = 0; i < 4; i++) {
            int idx = t + i * 256;       // 1024 float4 loads: 128 rows x 8 float4
            int r   = idx >> 3;
            int c4  = (idx & 7) * 4;
            int gr  = brow + r;
            float4 av = make_float4(0.f, 0.f, 0.f, 0.f);
            if (gr < N)
                av = *reinterpret_cast<const float4*>(g_m1 + (size_t)gr * D + kk * 32 + c4);
            As[r * 33 + c4 + 0] = av.x;
            As[r * 33 + c4 + 1] = av.y;
            As[r * 33 + c4 + 2] = av.z;
            As[r * 33 + c4 + 3] = av.w;
            float4 wv = *reinterpret_cast<const float4*>(W + (size_t)r * D + kk * 32 + c4);
            Ws[r * 33 + c4 + 0] = wv.x;
            Ws[r * 33 + c4 + 1] = wv.y;
            Ws[r * 33 + c4 + 2] = wv.z;
            Ws[r * 33 + c4 + 3] = wv.w;
        }
        __syncthreads();
#pragma unroll 8
        for (int k = 0; k < 32; k++) {
            float a[8], w[8];
#pragma unroll
            for (int u = 0; u < 8; u++) a[u] = As[(ty + 16 * u) * 33 + k];
#pragma unroll
            for (int v = 0; v < 8; v++) w[v] = Ws[(tx + 16 * v) * 33 + k];
#pragma unroll
            for (int u = 0; u < 8; u++)
#pragma unroll
                for (int v = 0; v < 8; v++) acc[u][v] += a[u] * w[v];
        }
    }

    float bv[8];
#pragma unroll
    for (int v = 0; v < 8; v++) bv[v] = bias[tx + 16 * v];

#pragma unroll
    for (int u = 0; u < 8; u++) {
        int gr = brow + ty + 16 * u;
        if (gr >= N) continue;
        float* o = out + (size_t)gr * 256 + 128;
#pragma unroll
        for (int v = 0; v < 8; v++) {
            float y = acc[u][v] + bv[v];
            y = (y >= 0.0f) ? y : 0.2f * y;
            o[tx + 16 * v] = y;
        }
    }
}

// ---------------------------------------------------------------------------
extern "C" void kernel_launch(void* const* d_in, const int* in_sizes, int n_in,
                              void* d_out, int out_size) {
    const int*   x       = (const int*)d_in[0];
    const int*   row     = (const int*)d_in[1];
    const int*   col     = (const int*)d_in[2];
    const float* vals    = (const float*)d_in[3];
    const float* embed_w = (const float*)d_in[4];
    const float* fc_w    = (const float*)d_in[5];
    const float* fc_b    = (const float*)d_in[6];
    float* out = (float*)d_out;

    const int N = in_sizes[0];
    const int E = in_sizes[1];

    // out[:, :128] = e
    copy_e_kernel<<<(N * 32 + 255) / 256, 256>>>(x, embed_w, out, N);

    // CSR build
    zero_counts_kernel<<<(N + 255) / 256, 256>>>(N);
    hist_kernel<<<(E + 255) / 256, 256>>>(row, E);
    scan_kernel<<<1, 1024>>>(N, E);
    scatter_kernel<<<(E + 255) / 256, 256>>>(row, col, vals, x, E);

    // fused SpMM + residual + dropout -> m1
    spmm_csr_kernel<<<(N * 32 + 255) / 256, 256>>>(x, embed_w, N);

    // FC + leaky relu -> out[:, 128:]
    gemm_kernel<<<(N + 127) / 128, 256>>>(fc_w, fc_b, out, N);
}

// round 6
// speedup vs baseline: 3.0287x; 1.4627x over previous
#include <cuda_runtime.h>

#define D 128
#define NMAX 100000
#define EMAX 3200000

#define SCAN_CHUNK 2048   // counts per scan block (1024 threads x 2)
#define MAX_CHUNKS ((NMAX + SCAN_CHUNK - 1) / SCAN_CHUNK)   // 49

// Scratch: m1[N][128], CSR build arrays.
__device__ float g_m1[(size_t)NMAX * D];
__device__ int   g_counts[NMAX];
__device__ int   g_row_start[NMAX + 1];
__device__ int   g_cursor[NMAX];
__device__ int   g_scol[EMAX];    // sorted source-node index (x[col[e]])
__device__ float g_sval[EMAX];    // sorted edge value
__device__ int   g_chunk_sums[MAX_CHUNKS];
__device__ int   g_chunk_offs[MAX_CHUNKS];

// ---------------------------------------------------------------------------
// JAX threefry2x32, key=(0,42); confirmed: ctr=(hi=0, lo=i), bits = x0.
// ---------------------------------------------------------------------------
__device__ __forceinline__ unsigned int threefry_x0_k42(unsigned int ctr_lo) {
    unsigned int x0 = 0u;
    unsigned int x1 = ctr_lo;
    const unsigned int ks1 = 42u;
    const unsigned int ks2 = 42u ^ 0x1BD11BDAu;
    x1 += ks1;
#define TF_ROUND(r) { x0 += x1; x1 = __funnelshift_l(x1, x1, (r)); x1 ^= x0; }
    TF_ROUND(13) TF_ROUND(15) TF_ROUND(26) TF_ROUND(6)
    x0 += ks1; x1 += ks2 + 1u;
    TF_ROUND(17) TF_ROUND(29) TF_ROUND(16) TF_ROUND(24)
    x0 += ks2; x1 += 0u + 2u;
    TF_ROUND(13) TF_ROUND(15) TF_ROUND(26) TF_ROUND(6)
    x0 += 0u;  x1 += ks1 + 3u;
    TF_ROUND(17) TF_ROUND(29) TF_ROUND(16) TF_ROUND(24)
    x0 += ks1; x1 += ks2 + 4u;
    TF_ROUND(13) TF_ROUND(15) TF_ROUND(26) TF_ROUND(6)
    x0 += ks2;
#undef TF_ROUND
    return x0;
}

__device__ __forceinline__ float drop_one(float v, unsigned int i) {
    unsigned int bits = threefry_x0_k42(i);
    float u = __uint_as_float(0x3f800000u | (bits >> 9)) - 1.0f;
    return (u < 0.9f) ? (v * (1.0f / 0.9f)) : 0.0f;
}

// ---------------------------------------------------------------------------
// Kernel 1: out[:, 0:128] = e = embed_w[x]
// ---------------------------------------------------------------------------
__global__ void copy_e_kernel(const int* __restrict__ x,
                              const float* __restrict__ embed_w,
                              float* __restrict__ out, int N) {
    int idx = blockIdx.x * blockDim.x + threadIdx.x;   // over N*32 float4s
    if (idx >= N * 32) return;
    int r  = idx >> 5;
    int c4 = idx & 31;
    int src = x[r];
    float4 v = reinterpret_cast<const float4*>(embed_w)[(size_t)src * 32 + c4];
    reinterpret_cast<float4*>(out)[(size_t)r * 64 + c4] = v;
}

// ---------------------------------------------------------------------------
// CSR build: zero counts -> histogram -> parallel scan (3 kernels) -> scatter
// ---------------------------------------------------------------------------
__global__ void zero_counts_kernel(int N) {
    int i = blockIdx.x * blockDim.x + threadIdx.x;
    if (i < N) g_counts[i] = 0;
}

__global__ void hist_kernel(const int* __restrict__ row, int E) {
    int e = blockIdx.x * blockDim.x + threadIdx.x;
    if (e < E) atomicAdd(&g_counts[row[e]], 1);
}

// Scan stage 1: each block reduces its 2048-count chunk to one sum.
__global__ __launch_bounds__(1024)
void scan_reduce_kernel(int N) {
    __shared__ int sh[1024];
    int b = blockIdx.x;
    int t = threadIdx.x;
    int base = b * SCAN_CHUNK;
    int i0 = base + 2 * t;
    int s = 0;
    if (i0 < N)     s += g_counts[i0];
    if (i0 + 1 < N) s += g_counts[i0 + 1];
    sh[t] = s;
    __syncthreads();
    for (int off = 512; off > 0; off >>= 1) {
        if (t < off) sh[t] += sh[t + off];
        __syncthreads();
    }
    if (t == 0) g_chunk_sums[b] = sh[0];
}

// Scan stage 2: single small block: exclusive scan of chunk sums.
__global__ void scan_sums_kernel(int nchunks) {
    __shared__ int sh[MAX_CHUNKS];
    int t = threadIdx.x;
    if (t < nchunks) sh[t] = g_chunk_sums[t];
    __syncthreads();
    if (t == 0) {
        int run = 0;
        for (int i = 0; i < nchunks; i++) { g_chunk_offs[i] = run; run += sh[i]; }
    }
}

// Scan stage 3: each block scans its chunk (exclusive), adds chunk offset,
// writes row_start and cursor.
__global__ __launch_bounds__(1024)
void scan_final_kernel(int N, int E) {
    __shared__ int sh[1024];
    int b = blockIdx.x;
    int t = threadIdx.x;
    int base = b * SCAN_CHUNK;
    int i0 = base + 2 * t;
    int c0 = (i0 < N)     ? g_counts[i0]     : 0;
    int c1 = (i0 + 1 < N) ? g_counts[i0 + 1] : 0;
    int pair = c0 + c1;
    sh[t] = pair;
    __syncthreads();
    // Hillis-Steele inclusive scan over 1024 pair-sums
    for (int off = 1; off < 1024; off <<= 1) {
        int v = (t >= off) ? sh[t - off] : 0;
        __syncthreads();
        sh[t] += v;
        __syncthreads();
    }
    int excl = sh[t] - pair + g_chunk_offs[b];   // exclusive prefix of element i0
    if (i0 < N)     { g_row_start[i0]     = excl;      g_cursor[i0]     = excl; }
    if (i0 + 1 < N) { g_row_start[i0 + 1] = excl + c0; g_cursor[i0 + 1] = excl + c0; }
    if (i0 == N - 1 || i0 + 1 == N - 1) g_row_start[N] = E;
}

__global__ void scatter_kernel(const int* __restrict__ row,
                               const int* __restrict__ col,
                               const float* __restrict__ vals,
                               const int* __restrict__ x, int E) {
    int e = blockIdx.x * blockDim.x + threadIdx.x;
    if (e >= E) return;
    int r = row[e];
    int pos = atomicAdd(&g_cursor[r], 1);
    g_scol[pos] = x[col[e]];
    g_sval[pos] = vals[e];
}

// ---------------------------------------------------------------------------
// Fused CSR SpMM + residual + dropout:
// m1[r] = dropout( e[r] + sum_j val_j * embed_w[colsrc_j] )
// One warp per row; each lane owns a float4 of the 128-wide row.
// ---------------------------------------------------------------------------
__global__ __launch_bounds__(256)
void spmm_csr_kernel(const int* __restrict__ x,
                     const float* __restrict__ embed_w, int N) {
    int warp = (blockIdx.x * blockDim.x + threadIdx.x) >> 5;
    if (warp >= N) return;
    int lane = threadIdx.x & 31;
    int r = warp;

    const float4* ew4 = reinterpret_cast<const float4*>(embed_w);

    // residual e[r]
    float4 acc = ew4[(size_t)x[r] * 32 + lane];

    int start = g_row_start[r];
    int end   = g_row_start[r + 1];

    for (int base = start; base < end; base += 32) {
        int j = base + lane;
        int  c = 0;
        float v = 0.0f;
        if (j < end) { c = g_scol[j]; v = g_sval[j]; }
        int m = min(32, end - base);
#pragma unroll 4
        for (int k = 0; k < m; k++) {
            int   ck = __shfl_sync(0xFFFFFFFFu, c, k);
            float vk = __shfl_sync(0xFFFFFFFFu, v, k);
            float4 ev = ew4[(size_t)ck * 32 + lane];
            acc.x += vk * ev.x;
            acc.y += vk * ev.y;
            acc.z += vk * ev.z;
            acc.w += vk * ev.w;
        }
    }

    // fused dropout (row-major element index)
    unsigned int i0 = (unsigned int)r * 128u + (unsigned int)lane * 4u;
    acc.x = drop_one(acc.x, i0 + 0u);
    acc.y = drop_one(acc.y, i0 + 1u);
    acc.z = drop_one(acc.z, i0 + 2u);
    acc.w = drop_one(acc.w, i0 + 3u);

    reinterpret_cast<float4*>(g_m1)[(size_t)r * 32 + lane] = acc;
}

// ---------------------------------------------------------------------------
// Kernel 4: x1 = leaky_relu(m1 @ W^T + b); out[:, 128:256] = x1
// ---------------------------------------------------------------------------
__global__ __launch_bounds__(256, 2)
void gemm_kernel(const float* __restrict__ W,
                 const float* __restrict__ bias,
                 float* __restrict__ out, int N) {
    __shared__ float As[128 * 33];   // [row][k] padded
    __shared__ float Ws[128 * 33];   // [outcol][k] padded
    const int t  = threadIdx.x;
    const int tx = t & 15;           // out-col group
    const int ty = t >> 4;           // row group
    const int brow = blockIdx.x * 128;

    float acc[8][8];
#pragma unroll
    for (int u = 0; u < 8; u++)
#pragma unroll
        for (int v = 0; v < 8; v++) acc[u][v] = 0.0f;

#pragma unroll 1
    for (int kk = 0; kk < 4; kk++) {
        if (kk) __syncthreads();
#pragma unroll
        for (int i = 0; i < 4; i++) {
            int idx = t + i * 256;       // 1024 float4 loads: 128 rows x 8 float4
            int r   = idx >> 3;
            int c4  = (idx & 7) * 4;
            int gr  = brow + r;
            float4 av = make_float4(0.f, 0.f, 0.f, 0.f);
            if (gr < N)
                av = *reinterpret_cast<const float4*>(g_m1 + (size_t)gr * D + kk * 32 + c4);
            As[r * 33 + c4 + 0] = av.x;
            As[r * 33 + c4 + 1] = av.y;
            As[r * 33 + c4 + 2] = av.z;
            As[r * 33 + c4 + 3] = av.w;
            float4 wv = *reinterpret_cast<const float4*>(W + (size_t)r * D + kk * 32 + c4);
            Ws[r * 33 + c4 + 0] = wv.x;
            Ws[r * 33 + c4 + 1] = wv.y;
            Ws[r * 33 + c4 + 2] = wv.z;
            Ws[r * 33 + c4 + 3] = wv.w;
        }
        __syncthreads();
#pragma unroll 8
        for (int k = 0; k < 32; k++) {
            float a[8], w[8];
#pragma unroll
            for (int u = 0; u < 8; u++) a[u] = As[(ty + 16 * u) * 33 + k];
#pragma unroll
            for (int v = 0; v < 8; v++) w[v] = Ws[(tx + 16 * v) * 33 + k];
#pragma unroll
            for (int u = 0; u < 8; u++)
#pragma unroll
                for (int v = 0; v < 8; v++) acc[u][v] += a[u] * w[v];
        }
    }

    float bv[8];
#pragma unroll
    for (int v = 0; v < 8; v++) bv[v] = bias[tx + 16 * v];

#pragma unroll
    for (int u = 0; u < 8; u++) {
        int gr = brow + ty + 16 * u;
        if (gr >= N) continue;
        float* o = out + (size_t)gr * 256 + 128;
#pragma unroll
        for (int v = 0; v < 8; v++) {
            float y = acc[u][v] + bv[v];
            y = (y >= 0.0f) ? y : 0.2f * y;
            o[tx + 16 * v] = y;
        }
    }
}

// ---------------------------------------------------------------------------
extern "C" void kernel_launch(void* const* d_in, const int* in_sizes, int n_in,
                              void* d_out, int out_size) {
    const int*   x       = (const int*)d_in[0];
    const int*   row     = (const int*)d_in[1];
    const int*   col     = (const int*)d_in[2];
    const float* vals    = (const float*)d_in[3];
    const float* embed_w = (const float*)d_in[4];
    const float* fc_w    = (const float*)d_in[5];
    const float* fc_b    = (const float*)d_in[6];
    float* out = (float*)d_out;

    const int N = in_sizes[0];
    const int E = in_sizes[1];
    const int nchunks = (N + SCAN_CHUNK - 1) / SCAN_CHUNK;

    // out[:, :128] = e
    copy_e_kernel<<<(N * 32 + 255) / 256, 256>>>(x, embed_w, out, N);

    // CSR build
    zero_counts_kernel<<<(N + 255) / 256, 256>>>(N);
    hist_kernel<<<(E + 255) / 256, 256>>>(row, E);
    scan_reduce_kernel<<<nchunks, 1024>>>(N);
    scan_sums_kernel<<<1, ((MAX_CHUNKS + 31) / 32) * 32>>>(nchunks);
    scan_final_kernel<<<nchunks, 1024>>>(N, E);
    scatter_kernel<<<(E + 255) / 256, 256>>>(row, col, vals, x, E);

    // fused SpMM + residual + dropout -> m1
    spmm_csr_kernel<<<(N * 32 + 255) / 256, 256>>>(x, embed_w, N);

    // FC + leaky relu -> out[:, 128:]
    gemm_kernel<<<(N + 127) / 128, 256>>>(fc_w, fc_b, out, N);
}

// round 7
// speedup vs baseline: 3.3649x; 1.1110x over previous
#include <cuda_runtime.h>

#define D 128
#define NMAX 100000
#define EMAX 3200000

#define SCAN_CHUNK 2048   // counts per scan block (1024 threads x 2)
#define MAX_CHUNKS ((NMAX + SCAN_CHUNK - 1) / SCAN_CHUNK)   // 49

// Scratch: m1[N][128], CSR build arrays.
__device__ float g_m1[(size_t)NMAX * D];
__device__ int   g_counts[NMAX];
__device__ int   g_row_start[NMAX + 1];
__device__ int   g_cursor[NMAX];
__device__ int2  g_edges[EMAX];   // .x = source-node idx (x[col[e]]), .y = val bits
__device__ int   g_chunk_sums[MAX_CHUNKS];
__device__ int   g_chunk_offs[MAX_CHUNKS];

// ---------------------------------------------------------------------------
// JAX threefry2x32, key=(0,42); confirmed: ctr=(hi=0, lo=i), bits = x0.
// ---------------------------------------------------------------------------
__device__ __forceinline__ unsigned int threefry_x0_k42(unsigned int ctr_lo) {
    unsigned int x0 = 0u;
    unsigned int x1 = ctr_lo;
    const unsigned int ks1 = 42u;
    const unsigned int ks2 = 42u ^ 0x1BD11BDAu;
    x1 += ks1;
#define TF_ROUND(r) { x0 += x1; x1 = __funnelshift_l(x1, x1, (r)); x1 ^= x0; }
    TF_ROUND(13) TF_ROUND(15) TF_ROUND(26) TF_ROUND(6)
    x0 += ks1; x1 += ks2 + 1u;
    TF_ROUND(17) TF_ROUND(29) TF_ROUND(16) TF_ROUND(24)
    x0 += ks2; x1 += 0u + 2u;
    TF_ROUND(13) TF_ROUND(15) TF_ROUND(26) TF_ROUND(6)
    x0 += 0u;  x1 += ks1 + 3u;
    TF_ROUND(17) TF_ROUND(29) TF_ROUND(16) TF_ROUND(24)
    x0 += ks1; x1 += ks2 + 4u;
    TF_ROUND(13) TF_ROUND(15) TF_ROUND(26) TF_ROUND(6)
    x0 += ks2;
#undef TF_ROUND
    return x0;
}

__device__ __forceinline__ float drop_one(float v, unsigned int i) {
    unsigned int bits = threefry_x0_k42(i);
    float u = __uint_as_float(0x3f800000u | (bits >> 9)) - 1.0f;
    return (u < 0.9f) ? (v * (1.0f / 0.9f)) : 0.0f;
}

// ---------------------------------------------------------------------------
// CSR build: zero counts -> histogram -> parallel scan (3 kernels) -> scatter
// ---------------------------------------------------------------------------
__global__ void zero_counts_kernel(int N) {
    int i = blockIdx.x * blockDim.x + threadIdx.x;
    if (i < N) g_counts[i] = 0;
}

__global__ void hist_kernel(const int* __restrict__ row, int E) {
    int q = blockIdx.x * blockDim.x + threadIdx.x;   // 4 edges per thread
    int e0 = q * 4;
    if (e0 + 3 < E) {
        int4 r4 = reinterpret_cast<const int4*>(row)[q];
        atomicAdd(&g_counts[r4.x], 1);
        atomicAdd(&g_counts[r4.y], 1);
        atomicAdd(&g_counts[r4.z], 1);
        atomicAdd(&g_counts[r4.w], 1);
    } else {
        for (int e = e0; e < E; e++) atomicAdd(&g_counts[row[e]], 1);
    }
}

// Scan stage 1: each block reduces its 2048-count chunk to one sum.
__global__ __launch_bounds__(1024)
void scan_reduce_kernel(int N) {
    __shared__ int sh[1024];
    int b = blockIdx.x;
    int t = threadIdx.x;
    int base = b * SCAN_CHUNK;
    int i0 = base + 2 * t;
    int s = 0;
    if (i0 < N)     s += g_counts[i0];
    if (i0 + 1 < N) s += g_counts[i0 + 1];
    sh[t] = s;
    __syncthreads();
    for (int off = 512; off > 0; off >>= 1) {
        if (t < off) sh[t] += sh[t + off];
        __syncthreads();
    }
    if (t == 0) g_chunk_sums[b] = sh[0];
}

// Scan stage 2: single small block: exclusive scan of chunk sums.
__global__ void scan_sums_kernel(int nchunks) {
    __shared__ int sh[MAX_CHUNKS];
    int t = threadIdx.x;
    if (t < nchunks) sh[t] = g_chunk_sums[t];
    __syncthreads();
    if (t == 0) {
        int run = 0;
        for (int i = 0; i < nchunks; i++) { g_chunk_offs[i] = run; run += sh[i]; }
    }
}

// Scan stage 3: each block scans its chunk (exclusive), adds chunk offset,
// writes row_start and cursor.
__global__ __launch_bounds__(1024)
void scan_final_kernel(int N, int E) {
    __shared__ int sh[1024];
    int b = blockIdx.x;
    int t = threadIdx.x;
    int base = b * SCAN_CHUNK;
    int i0 = base + 2 * t;
    int c0 = (i0 < N)     ? g_counts[i0]     : 0;
    int c1 = (i0 + 1 < N) ? g_counts[i0 + 1] : 0;
    int pair = c0 + c1;
    sh[t] = pair;
    __syncthreads();
    for (int off = 1; off < 1024; off <<= 1) {
        int v = (t >= off) ? sh[t - off] : 0;
        __syncthreads();
        sh[t] += v;
        __syncthreads();
    }
    int excl = sh[t] - pair + g_chunk_offs[b];
    if (i0 < N)     { g_row_start[i0]     = excl;      g_cursor[i0]     = excl; }
    if (i0 + 1 < N) { g_row_start[i0 + 1] = excl + c0; g_cursor[i0 + 1] = excl + c0; }
    if (i0 == N - 1 || i0 + 1 == N - 1) g_row_start[N] = E;
}

__global__ void scatter_kernel(const int* __restrict__ row,
                               const int* __restrict__ col,
                               const float* __restrict__ vals,
                               const int* __restrict__ x, int E) {
    int e = blockIdx.x * blockDim.x + threadIdx.x;
    if (e >= E) return;
    int r = row[e];
    int pos = atomicAdd(&g_cursor[r], 1);
    g_edges[pos] = make_int2(x[col[e]], __float_as_int(vals[e]));
}

// ---------------------------------------------------------------------------
// Fused CSR SpMM + residual + dropout + e-copy:
//   out[r, 0:128] = e[r]
//   m1[r] = dropout( e[r] + sum_j val_j * embed_w[src_j] )
// One warp per row; each lane owns a float4 of the 128-wide row.
// ---------------------------------------------------------------------------
__global__ __launch_bounds__(256)
void spmm_csr_kernel(const int* __restrict__ x,
                     const float* __restrict__ embed_w,
                     float* __restrict__ out, int N) {
    int warp = (blockIdx.x * blockDim.x + threadIdx.x) >> 5;
    if (warp >= N) return;
    int lane = threadIdx.x & 31;
    int r = warp;

    const float4* ew4 = reinterpret_cast<const float4*>(embed_w);

    // residual e[r]; also emit first output half
    float4 acc = ew4[(size_t)x[r] * 32 + lane];
    reinterpret_cast<float4*>(out)[(size_t)r * 64 + lane] = acc;

    int start = g_row_start[r];
    int end   = g_row_start[r + 1];

    for (int base = start; base < end; base += 32) {
        int j = base + lane;
        int  c = 0;
        float v = 0.0f;
        if (j < end) {
            int2 ed = g_edges[j];
            c = ed.x;
            v = __int_as_float(ed.y);
        }
        int m = min(32, end - base);
#pragma unroll 4
        for (int k = 0; k < m; k++) {
            int   ck = __shfl_sync(0xFFFFFFFFu, c, k);
            float vk = __shfl_sync(0xFFFFFFFFu, v, k);
            float4 ev = ew4[(size_t)ck * 32 + lane];
            acc.x += vk * ev.x;
            acc.y += vk * ev.y;
            acc.z += vk * ev.z;
            acc.w += vk * ev.w;
        }
    }

    // fused dropout (row-major element index)
    unsigned int i0 = (unsigned int)r * 128u + (unsigned int)lane * 4u;
    acc.x = drop_one(acc.x, i0 + 0u);
    acc.y = drop_one(acc.y, i0 + 1u);
    acc.z = drop_one(acc.z, i0 + 2u);
    acc.w = drop_one(acc.w, i0 + 3u);

    reinterpret_cast<float4*>(g_m1)[(size_t)r * 32 + lane] = acc;
}

// ---------------------------------------------------------------------------
// GEMM: x1 = leaky_relu(m1 @ W^T + b); out[:, 128:256] = x1
// ---------------------------------------------------------------------------
__global__ __launch_bounds__(256, 2)
void gemm_kernel(const float* __restrict__ W,
                 const float* __restrict__ bias,
                 float* __restrict__ out, int N) {
    __shared__ float As[128 * 33];   // [row][k] padded
    __shared__ float Ws[128 * 33];   // [outcol][k] padded
    const int t  = threadIdx.x;
    const int tx = t & 15;           // out-col group
    const int ty = t >> 4;           // row group
    const int brow = blockIdx.x * 128;

    float acc[8][8];
#pragma unroll
    for (int u = 0; u < 8; u++)
#pragma unroll
        for (int v = 0; v < 8; v++) acc[u][v] = 0.0f;

#pragma unroll 1
    for (int kk = 0; kk < 4; kk++) {
        if (kk) __syncthreads();
#pragma unroll
        for (int i = 0; i < 4; i++) {
            int idx = t + i * 256;
            int r   = idx >> 3;
            int c4  = (idx & 7) * 4;
            int gr  = brow + r;
            float4 av = make_float4(0.f, 0.f, 0.f, 0.f);
            if (gr < N)
                av = *reinterpret_cast<const float4*>(g_m1 + (size_t)gr * D + kk * 32 + c4);
            As[r * 33 + c4 + 0] = av.x;
            As[r * 33 + c4 + 1] = av.y;
            As[r * 33 + c4 + 2] = av.z;
            As[r * 33 + c4 + 3] = av.w;
            float4 wv = *reinterpret_cast<const float4*>(W + (size_t)r * D + kk * 32 + c4);
            Ws[r * 33 + c4 + 0] = wv.x;
            Ws[r * 33 + c4 + 1] = wv.y;
            Ws[r * 33 + c4 + 2] = wv.z;
            Ws[r * 33 + c4 + 3] = wv.w;
        }
        __syncthreads();
#pragma unroll 8
        for (int k = 0; k < 32; k++) {
            float a[8], w[8];
#pragma unroll
            for (int u = 0; u < 8; u++) a[u] = As[(ty + 16 * u) * 33 + k];
#pragma unroll
            for (int v = 0; v < 8; v++) w[v] = Ws[(tx + 16 * v) * 33 + k];
#pragma unroll
            for (int u = 0; u < 8; u++)
#pragma unroll
                for (int v = 0; v < 8; v++) acc[u][v] += a[u] * w[v];
        }
    }

    float bv[8];
#pragma unroll
    for (int v = 0; v < 8; v++) bv[v] = bias[tx + 16 * v];

#pragma unroll
    for (int u = 0; u < 8; u++) {
        int gr = brow + ty + 16 * u;
        if (gr >= N) continue;
        float* o = out + (size_t)gr * 256 + 128;
#pragma unroll
        for (int v = 0; v < 8; v++) {
            float y = acc[u][v] + bv[v];
            y = (y >= 0.0f) ? y : 0.2f * y;
            o[tx + 16 * v] = y;
        }
    }
}

// ---------------------------------------------------------------------------
extern "C" void kernel_launch(void* const* d_in, const int* in_sizes, int n_in,
                              void* d_out, int out_size) {
    const int*   x       = (const int*)d_in[0];
    const int*   row     = (const int*)d_in[1];
    const int*   col     = (const int*)d_in[2];
    const float* vals    = (const float*)d_in[3];
    const float* embed_w = (const float*)d_in[4];
    const float* fc_w    = (const float*)d_in[5];
    const float* fc_b    = (const float*)d_in[6];
    float* out = (float*)d_out;

    const int N = in_sizes[0];
    const int E = in_sizes[1];
    const int nchunks = (N + SCAN_CHUNK - 1) / SCAN_CHUNK;

    // CSR build
    zero_counts_kernel<<<(N + 255) / 256, 256>>>(N);
    hist_kernel<<<((E + 3) / 4 + 255) / 256, 256>>>(row, E);
    scan_reduce_kernel<<<nchunks, 1024>>>(N);
    scan_sums_kernel<<<1, ((MAX_CHUNKS + 31) / 32) * 32>>>(nchunks);
    scan_final_kernel<<<nchunks, 1024>>>(N, E);
    scatter_kernel<<<(E + 255) / 256, 256>>>(row, col, vals, x, E);

    // fused SpMM + residual + dropout + e-copy
    spmm_csr_kernel<<<(N * 32 + 255) / 256, 256>>>(x, embed_w, out, N);

    // FC + leaky relu -> out[:, 128:]
    gemm_kernel<<<(N + 127) / 128, 256>>>(fc_w, fc_b, out, N);
}

// round 8
// speedup vs baseline: 3.4111x; 1.0137x over previous
#include <cuda_runtime.h>

#define D 128
#define NMAX 100000
#define EMAX 3200000

#define SCAN_CHUNK 2048
#define MAX_CHUNKS ((NMAX + SCAN_CHUNK - 1) / SCAN_CHUNK)   // 49

__device__ float g_m1[(size_t)NMAX * D];
__device__ int   g_counts[NMAX];
__device__ int   g_row_start[NMAX + 1];
__device__ int   g_cursor[NMAX];
__device__ int2  g_edges[EMAX];   // .x = source-node idx, .y = val bits
__device__ int   g_chunk_sums[MAX_CHUNKS];
__device__ int   g_chunk_offs[MAX_CHUNKS];

// ---------------------------------------------------------------------------
// JAX threefry2x32, key=(0,42); confirmed: ctr=(hi=0, lo=i), bits = x0.
// ---------------------------------------------------------------------------
__device__ __forceinline__ unsigned int threefry_x0_k42(unsigned int ctr_lo) {
    unsigned int x0 = 0u;
    unsigned int x1 = ctr_lo;
    const unsigned int ks1 = 42u;
    const unsigned int ks2 = 42u ^ 0x1BD11BDAu;
    x1 += ks1;
#define TF_ROUND(r) { x0 += x1; x1 = __funnelshift_l(x1, x1, (r)); x1 ^= x0; }
    TF_ROUND(13) TF_ROUND(15) TF_ROUND(26) TF_ROUND(6)
    x0 += ks1; x1 += ks2 + 1u;
    TF_ROUND(17) TF_ROUND(29) TF_ROUND(16) TF_ROUND(24)
    x0 += ks2; x1 += 0u + 2u;
    TF_ROUND(13) TF_ROUND(15) TF_ROUND(26) TF_ROUND(6)
    x0 += 0u;  x1 += ks1 + 3u;
    TF_ROUND(17) TF_ROUND(29) TF_ROUND(16) TF_ROUND(24)
    x0 += ks1; x1 += ks2 + 4u;
    TF_ROUND(13) TF_ROUND(15) TF_ROUND(26) TF_ROUND(6)
    x0 += ks2;
#undef TF_ROUND
    return x0;
}

__device__ __forceinline__ float drop_one(float v, unsigned int i) {
    unsigned int bits = threefry_x0_k42(i);
    float u = __uint_as_float(0x3f800000u | (bits >> 9)) - 1.0f;
    return (u < 0.9f) ? (v * (1.0f / 0.9f)) : 0.0f;
}

// ---------------------------------------------------------------------------
// CSR build
// ---------------------------------------------------------------------------
__global__ void zero_counts_kernel(int N) {
    int i = blockIdx.x * blockDim.x + threadIdx.x;
    if (i < N) g_counts[i] = 0;
}

__global__ void hist_kernel(const int* __restrict__ row, int E) {
    int q = blockIdx.x * blockDim.x + threadIdx.x;
    int e0 = q * 4;
    if (e0 + 3 < E) {
        int4 r4 = reinterpret_cast<const int4*>(row)[q];
        atomicAdd(&g_counts[r4.x], 1);
        atomicAdd(&g_counts[r4.y], 1);
        atomicAdd(&g_counts[r4.z], 1);
        atomicAdd(&g_counts[r4.w], 1);
    } else {
        for (int e = e0; e < E; e++) atomicAdd(&g_counts[row[e]], 1);
    }
}

__global__ __launch_bounds__(1024)
void scan_reduce_kernel(int N) {
    __shared__ int sh[1024];
    int b = blockIdx.x, t = threadIdx.x;
    int i0 = b * SCAN_CHUNK + 2 * t;
    int s = 0;
    if (i0 < N)     s += g_counts[i0];
    if (i0 + 1 < N) s += g_counts[i0 + 1];
    sh[t] = s;
    __syncthreads();
    for (int off = 512; off > 0; off >>= 1) {
        if (t < off) sh[t] += sh[t + off];
        __syncthreads();
    }
    if (t == 0) g_chunk_sums[b] = sh[0];
}

__global__ void scan_sums_kernel(int nchunks) {
    int t = threadIdx.x;
    if (t == 0) {
        int run = 0;
        for (int i = 0; i < nchunks; i++) { g_chunk_offs[i] = run; run += g_chunk_sums[i]; }
    }
}

__global__ __launch_bounds__(1024)
void scan_final_kernel(int N, int E) {
    __shared__ int sh[1024];
    int b = blockIdx.x, t = threadIdx.x;
    int i0 = b * SCAN_CHUNK + 2 * t;
    int c0 = (i0 < N)     ? g_counts[i0]     : 0;
    int c1 = (i0 + 1 < N) ? g_counts[i0 + 1] : 0;
    int pair = c0 + c1;
    sh[t] = pair;
    __syncthreads();
    for (int off = 1; off < 1024; off <<= 1) {
        int v = (t >= off) ? sh[t - off] : 0;
        __syncthreads();
        sh[t] += v;
        __syncthreads();
    }
    int excl = sh[t] - pair + g_chunk_offs[b];
    if (i0 < N)     { g_row_start[i0]     = excl;      g_cursor[i0]     = excl; }
    if (i0 + 1 < N) { g_row_start[i0 + 1] = excl + c0; g_cursor[i0 + 1] = excl + c0; }
    if (i0 == N - 1 || i0 + 1 == N - 1) g_row_start[N] = E;
}

__global__ void scatter_kernel(const int* __restrict__ row,
                               const int* __restrict__ col,
                               const float* __restrict__ vals,
                               const int* __restrict__ x, int E) {
    int e = blockIdx.x * blockDim.x + threadIdx.x;
    if (e >= E) return;
    int r = row[e];
    int pos = atomicAdd(&g_cursor[r], 1);
    g_edges[pos] = make_int2(x[col[e]], __float_as_int(vals[e]));
}

// ---------------------------------------------------------------------------
// Fused CSR SpMM + residual + dropout + e-copy (at L2 roofline)
// ---------------------------------------------------------------------------
__global__ __launch_bounds__(256)
void spmm_csr_kernel(const int* __restrict__ x,
                     const float* __restrict__ embed_w,
                     float* __restrict__ out, int N) {
    int warp = (blockIdx.x * blockDim.x + threadIdx.x) >> 5;
    if (warp >= N) return;
    int lane = threadIdx.x & 31;
    int r = warp;

    const float4* ew4 = reinterpret_cast<const float4*>(embed_w);

    float4 acc = ew4[(size_t)x[r] * 32 + lane];
    reinterpret_cast<float4*>(out)[(size_t)r * 64 + lane] = acc;

    int start = g_row_start[r];
    int end   = g_row_start[r + 1];

    for (int base = start; base < end; base += 32) {
        int j = base + lane;
        int  c = 0;
        float v = 0.0f;
        if (j < end) {
            int2 ed = g_edges[j];
            c = ed.x;
            v = __int_as_float(ed.y);
        }
        int m = min(32, end - base);
#pragma unroll 4
        for (int k = 0; k < m; k++) {
            int   ck = __shfl_sync(0xFFFFFFFFu, c, k);
            float vk = __shfl_sync(0xFFFFFFFFu, v, k);
            float4 ev = ew4[(size_t)ck * 32 + lane];
            acc.x += vk * ev.x;
            acc.y += vk * ev.y;
            acc.z += vk * ev.z;
            acc.w += vk * ev.w;
        }
    }

    unsigned int i0 = (unsigned int)r * 128u + (unsigned int)lane * 4u;
    acc.x = drop_one(acc.x, i0 + 0u);
    acc.y = drop_one(acc.y, i0 + 1u);
    acc.z = drop_one(acc.z, i0 + 2u);
    acc.w = drop_one(acc.w, i0 + 3u);

    reinterpret_cast<float4*>(g_m1)[(size_t)r * 32 + lane] = acc;
}

// ---------------------------------------------------------------------------
// GEMM: x1 = leaky_relu(m1 @ W^T + b); out[:, 128:256] = x1
// Transposed smem tiles [k][m] / [k][n] with pad 132 -> inner loop is
// 4x LDS.128 + 64 FFMA per k. Thread tile: rows {ty*4..+3, +64..}, cols same in tx.
// ---------------------------------------------------------------------------
#define KPAD 132

__global__ __launch_bounds__(256, 2)
void gemm_kernel(const float* __restrict__ W,
                 const float* __restrict__ bias,
                 float* __restrict__ out, int N) {
    __shared__ float As[32 * KPAD];   // [k][row]
    __shared__ float Ws[32 * KPAD];   // [k][outcol]
    const int t  = threadIdx.x;
    const int tx = t & 15;
    const int ty = t >> 4;
    const int brow = blockIdx.x * 128;

    float acc[8][8];
#pragma unroll
    for (int u = 0; u < 8; u++)
#pragma unroll
        for (int v = 0; v < 8; v++) acc[u][v] = 0.0f;

#pragma unroll 1
    for (int kk = 0; kk < 4; kk++) {
        if (kk) __syncthreads();
#pragma unroll
        for (int i = 0; i < 4; i++) {
            int idx = t + i * 256;       // 1024: 128 rows x 8 k-float4s
            int r   = idx >> 3;          // 0..127
            int c4  = (idx & 7) * 4;     // k within chunk
            int gr  = brow + r;
            float4 av = make_float4(0.f, 0.f, 0.f, 0.f);
            if (gr < N)
                av = *reinterpret_cast<const float4*>(g_m1 + (size_t)gr * D + kk * 32 + c4);
            As[(c4 + 0) * KPAD + r] = av.x;
            As[(c4 + 1) * KPAD + r] = av.y;
            As[(c4 + 2) * KPAD + r] = av.z;
            As[(c4 + 3) * KPAD + r] = av.w;
            float4 wv = *reinterpret_cast<const float4*>(W + (size_t)r * D + kk * 32 + c4);
            Ws[(c4 + 0) * KPAD + r] = wv.x;
            Ws[(c4 + 1) * KPAD + r] = wv.y;
            Ws[(c4 + 2) * KPAD + r] = wv.z;
            Ws[(c4 + 3) * KPAD + r] = wv.w;
        }
        __syncthreads();
#pragma unroll
        for (int k = 0; k < 32; k++) {
            float4 aLo = *reinterpret_cast<const float4*>(&As[k * KPAD + ty * 4]);
            float4 aHi = *reinterpret_cast<const float4*>(&As[k * KPAD + ty * 4 + 64]);
            float4 wLo = *reinterpret_cast<const float4*>(&Ws[k * KPAD + tx * 4]);
            float4 wHi = *reinterpret_cast<const float4*>(&Ws[k * KPAD + tx * 4 + 64]);
            float a[8] = {aLo.x, aLo.y, aLo.z, aLo.w, aHi.x, aHi.y, aHi.z, aHi.w};
            float w[8] = {wLo.x, wLo.y, wLo.z, wLo.w, wHi.x, wHi.y, wHi.z, wHi.w};
#pragma unroll
            for (int u = 0; u < 8; u++)
#pragma unroll
                for (int v = 0; v < 8; v++) acc[u][v] += a[u] * w[v];
        }
    }

    float bv[8];
#pragma unroll
    for (int v = 0; v < 4; v++) {
        bv[v]     = bias[tx * 4 + v];
        bv[v + 4] = bias[tx * 4 + 64 + v];
    }

#pragma unroll
    for (int u = 0; u < 8; u++) {
        int gr = brow + ((u < 4) ? (ty * 4 + u) : (ty * 4 + 64 + u - 4));
        if (gr >= N) continue;
        float* o = out + (size_t)gr * 256 + 128;
        float y[8];
#pragma unroll
        for (int v = 0; v < 8; v++) {
            float z = acc[u][v] + bv[v];
            y[v] = (z >= 0.0f) ? z : 0.2f * z;
        }
        *reinterpret_cast<float4*>(o + tx * 4)      = make_float4(y[0], y[1], y[2], y[3]);
        *reinterpret_cast<float4*>(o + tx * 4 + 64) = make_float4(y[4], y[5], y[6], y[7]);
    }
}

// ---------------------------------------------------------------------------
extern "C" void kernel_launch(void* const* d_in, const int* in_sizes, int n_in,
                              void* d_out, int out_size) {
    const int*   x       = (const int*)d_in[0];
    const int*   row     = (const int*)d_in[1];
    const int*   col     = (const int*)d_in[2];
    const float* vals    = (const float*)d_in[3];
    const float* embed_w = (const float*)d_in[4];
    const float* fc_w    = (const float*)d_in[5];
    const float* fc_b    = (const float*)d_in[6];
    float* out = (float*)d_out;

    const int N = in_sizes[0];
    const int E = in_sizes[1];
    const int nchunks = (N + SCAN_CHUNK - 1) / SCAN_CHUNK;

    zero_counts_kernel<<<(N + 255) / 256, 256>>>(N);
    hist_kernel<<<((E + 3) / 4 + 255) / 256, 256>>>(row, E);
    scan_reduce_kernel<<<nchunks, 1024>>>(N);
    scan_sums_kernel<<<1, 32>>>(nchunks);
    scan_final_kernel<<<nchunks, 1024>>>(N, E);
    scatter_kernel<<<(E + 255) / 256, 256>>>(row, col, vals, x, E);

    spmm_csr_kernel<<<(N * 32 + 255) / 256, 256>>>(x, embed_w, out, N);

    gemm_kernel<<<(N + 127) / 128, 256>>>(fc_w, fc_b, out, N);
}

// round 9
// speedup vs baseline: 3.4602x; 1.0144x over previous
#include <cuda_runtime.h>

#define D 128
#define NMAX 100000
#define EMAX 3200000

#define SCAN_CHUNK 2048
#define MAX_CHUNKS ((NMAX + SCAN_CHUNK - 1) / SCAN_CHUNK)   // 49

__device__ float g_m1[(size_t)NMAX * D];
__device__ int   g_counts[NMAX];
__device__ int   g_row_start[NMAX + 1];
__device__ int   g_cursor[NMAX];
__device__ int2  g_edges[EMAX];   // .x = source-node idx, .y = val bits
__device__ int   g_chunk_sums[MAX_CHUNKS];
__device__ int   g_chunk_offs[MAX_CHUNKS];

// ---------------------------------------------------------------------------
// JAX threefry2x32, key=(0,42); confirmed: ctr=(hi=0, lo=i), bits = x0.
// ---------------------------------------------------------------------------
__device__ __forceinline__ unsigned int threefry_x0_k42(unsigned int ctr_lo) {
    unsigned int x0 = 0u;
    unsigned int x1 = ctr_lo;
    const unsigned int ks1 = 42u;
    const unsigned int ks2 = 42u ^ 0x1BD11BDAu;
    x1 += ks1;
#define TF_ROUND(r) { x0 += x1; x1 = __funnelshift_l(x1, x1, (r)); x1 ^= x0; }
    TF_ROUND(13) TF_ROUND(15) TF_ROUND(26) TF_ROUND(6)
    x0 += ks1; x1 += ks2 + 1u;
    TF_ROUND(17) TF_ROUND(29) TF_ROUND(16) TF_ROUND(24)
    x0 += ks2; x1 += 0u + 2u;
    TF_ROUND(13) TF_ROUND(15) TF_ROUND(26) TF_ROUND(6)
    x0 += 0u;  x1 += ks1 + 3u;
    TF_ROUND(17) TF_ROUND(29) TF_ROUND(16) TF_ROUND(24)
    x0 += ks1; x1 += ks2 + 4u;
    TF_ROUND(13) TF_ROUND(15) TF_ROUND(26) TF_ROUND(6)
    x0 += ks2;
#undef TF_ROUND
    return x0;
}

__device__ __forceinline__ float drop_one(float v, unsigned int i) {
    unsigned int bits = threefry_x0_k42(i);
    float u = __uint_as_float(0x3f800000u | (bits >> 9)) - 1.0f;
    return (u < 0.9f) ? (v * (1.0f / 0.9f)) : 0.0f;
}

// ---------------------------------------------------------------------------
// packed fp32x2 helpers (sm_100+): FFMA2 = 2 exact fp32 FMAs per instruction
// ---------------------------------------------------------------------------
__device__ __forceinline__ unsigned long long pack_dup(float x) {
    unsigned long long r;
    asm("mov.b64 %0, {%1, %1};" : "=l"(r) : "f"(x));
    return r;
}
__device__ __forceinline__ void ffma2(unsigned long long& d,
                                      unsigned long long a,
                                      unsigned long long b) {
    asm("fma.rn.f32x2 %0, %1, %2, %0;" : "+l"(d) : "l"(a), "l"(b));
}
__device__ __forceinline__ float2 unpack2(unsigned long long p) {
    float lo, hi;
    asm("mov.b64 {%0, %1}, %2;" : "=f"(lo), "=f"(hi) : "l"(p));
    return make_float2(lo, hi);
}

// ---------------------------------------------------------------------------
// CSR build
// ---------------------------------------------------------------------------
__global__ void zero_counts_kernel(int N) {
    int i = blockIdx.x * blockDim.x + threadIdx.x;
    if (i < N) g_counts[i] = 0;
}

__global__ void hist_kernel(const int* __restrict__ row, int E) {
    int q = blockIdx.x * blockDim.x + threadIdx.x;
    int e0 = q * 4;
    if (e0 + 3 < E) {
        int4 r4 = reinterpret_cast<const int4*>(row)[q];
        atomicAdd(&g_counts[r4.x], 1);
        atomicAdd(&g_counts[r4.y], 1);
        atomicAdd(&g_counts[r4.z], 1);
        atomicAdd(&g_counts[r4.w], 1);
    } else {
        for (int e = e0; e < E; e++) atomicAdd(&g_counts[row[e]], 1);
    }
}

__global__ __launch_bounds__(1024)
void scan_reduce_kernel(int N) {
    __shared__ int sh[1024];
    int b = blockIdx.x, t = threadIdx.x;
    int i0 = b * SCAN_CHUNK + 2 * t;
    int s = 0;
    if (i0 < N)     s += g_counts[i0];
    if (i0 + 1 < N) s += g_counts[i0 + 1];
    sh[t] = s;
    __syncthreads();
    for (int off = 512; off > 0; off >>= 1) {
        if (t < off) sh[t] += sh[t + off];
        __syncthreads();
    }
    if (t == 0) g_chunk_sums[b] = sh[0];
}

__global__ void scan_sums_kernel(int nchunks) {
    if (threadIdx.x == 0) {
        int run = 0;
        for (int i = 0; i < nchunks; i++) { g_chunk_offs[i] = run; run += g_chunk_sums[i]; }
    }
}

__global__ __launch_bounds__(1024)
void scan_final_kernel(int N, int E) {
    __shared__ int sh[1024];
    int b = blockIdx.x, t = threadIdx.x;
    int i0 = b * SCAN_CHUNK + 2 * t;
    int c0 = (i0 < N)     ? g_counts[i0]     : 0;
    int c1 = (i0 + 1 < N) ? g_counts[i0 + 1] : 0;
    int pair = c0 + c1;
    sh[t] = pair;
    __syncthreads();
    for (int off = 1; off < 1024; off <<= 1) {
        int v = (t >= off) ? sh[t - off] : 0;
        __syncthreads();
        sh[t] += v;
        __syncthreads();
    }
    int excl = sh[t] - pair + g_chunk_offs[b];
    if (i0 < N)     { g_row_start[i0]     = excl;      g_cursor[i0]     = excl; }
    if (i0 + 1 < N) { g_row_start[i0 + 1] = excl + c0; g_cursor[i0 + 1] = excl + c0; }
    if (i0 == N - 1 || i0 + 1 == N - 1) g_row_start[N] = E;
}

__global__ void scatter_kernel(const int* __restrict__ row,
                               const int* __restrict__ col,
                               const float* __restrict__ vals,
                               const int* __restrict__ x, int E) {
    int e = blockIdx.x * blockDim.x + threadIdx.x;
    if (e >= E) return;
    int r = row[e];
    int pos = atomicAdd(&g_cursor[r], 1);
    g_edges[pos] = make_int2(x[col[e]], __float_as_int(vals[e]));
}

// ---------------------------------------------------------------------------
// Fused CSR SpMM + residual + dropout + e-copy (at L2 roofline)
// ---------------------------------------------------------------------------
__global__ __launch_bounds__(256)
void spmm_csr_kernel(const int* __restrict__ x,
                     const float* __restrict__ embed_w,
                     float* __restrict__ out, int N) {
    int warp = (blockIdx.x * blockDim.x + threadIdx.x) >> 5;
    if (warp >= N) return;
    int lane = threadIdx.x & 31;
    int r = warp;

    const float4* ew4 = reinterpret_cast<const float4*>(embed_w);

    float4 acc = ew4[(size_t)x[r] * 32 + lane];
    reinterpret_cast<float4*>(out)[(size_t)r * 64 + lane] = acc;

    int start = g_row_start[r];
    int end   = g_row_start[r + 1];

    for (int base = start; base < end; base += 32) {
        int j = base + lane;
        int  c = 0;
        float v = 0.0f;
        if (j < end) {
            int2 ed = g_edges[j];
            c = ed.x;
            v = __int_as_float(ed.y);
        }
        int m = min(32, end - base);
#pragma unroll 4
        for (int k = 0; k < m; k++) {
            int   ck = __shfl_sync(0xFFFFFFFFu, c, k);
            float vk = __shfl_sync(0xFFFFFFFFu, v, k);
            float4 ev = ew4[(size_t)ck * 32 + lane];
            acc.x += vk * ev.x;
            acc.y += vk * ev.y;
            acc.z += vk * ev.z;
            acc.w += vk * ev.w;
        }
    }

    unsigned int i0 = (unsigned int)r * 128u + (unsigned int)lane * 4u;
    acc.x = drop_one(acc.x, i0 + 0u);
    acc.y = drop_one(acc.y, i0 + 1u);
    acc.z = drop_one(acc.z, i0 + 2u);
    acc.w = drop_one(acc.w, i0 + 3u);

    reinterpret_cast<float4*>(g_m1)[(size_t)r * 32 + lane] = acc;
}

// ---------------------------------------------------------------------------
// GEMM via FFMA2: x1 = leaky_relu(m1 @ W^T + b); out[:, 128:256] = x1
// Smem tiles [k][m]/[k][n] (pad 132). Per k: 4x LDS.128, 8 packs, 32 FFMA2.
// acc2[u][v2] holds 2 output columns packed; exact fp32.
// ---------------------------------------------------------------------------
#define KPAD 132

__global__ __launch_bounds__(256, 2)
void gemm_kernel(const float* __restrict__ W,
                 const float* __restrict__ bias,
                 float* __restrict__ out, int N) {
    __shared__ float As[32 * KPAD];   // [k][row]
    __shared__ float Ws[32 * KPAD];   // [k][outcol]
    const int t  = threadIdx.x;
    const int tx = t & 15;
    const int ty = t >> 4;
    const int brow = blockIdx.x * 128;

    unsigned long long acc2[8][4];
#pragma unroll
    for (int u = 0; u < 8; u++)
#pragma unroll
        for (int v = 0; v < 4; v++) acc2[u][v] = 0ull;

#pragma unroll 1
    for (int kk = 0; kk < 4; kk++) {
        if (kk) __syncthreads();
#pragma unroll
        for (int i = 0; i < 4; i++) {
            int idx = t + i * 256;       // 1024: 128 rows x 8 k-float4s
            int r   = idx >> 3;
            int c4  = (idx & 7) * 4;
            int gr  = brow + r;
            float4 av = make_float4(0.f, 0.f, 0.f, 0.f);
            if (gr < N)
                av = *reinterpret_cast<const float4*>(g_m1 + (size_t)gr * D + kk * 32 + c4);
            As[(c4 + 0) * KPAD + r] = av.x;
            As[(c4 + 1) * KPAD + r] = av.y;
            As[(c4 + 2) * KPAD + r] = av.z;
            As[(c4 + 3) * KPAD + r] = av.w;
            float4 wv = *reinterpret_cast<const float4*>(W + (size_t)r * D + kk * 32 + c4);
            Ws[(c4 + 0) * KPAD + r] = wv.x;
            Ws[(c4 + 1) * KPAD + r] = wv.y;
            Ws[(c4 + 2) * KPAD + r] = wv.z;
            Ws[(c4 + 3) * KPAD + r] = wv.w;
        }
        __syncthreads();
#pragma unroll
        for (int k = 0; k < 32; k++) {
            float4 aLo = *reinterpret_cast<const float4*>(&As[k * KPAD + ty * 4]);
            float4 aHi = *reinterpret_cast<const float4*>(&As[k * KPAD + ty * 4 + 64]);
            // w pairs: (tx*4, tx*4+1), (tx*4+2, tx*4+3), (+64 same)
            const unsigned long long* wp =
                reinterpret_cast<const unsigned long long*>(&Ws[k * KPAD]);
            unsigned long long w0 = wp[tx * 2];
            unsigned long long w1 = wp[tx * 2 + 1];
            unsigned long long w2 = wp[tx * 2 + 32];
            unsigned long long w3 = wp[tx * 2 + 33];
            float a[8] = {aLo.x, aLo.y, aLo.z, aLo.w, aHi.x, aHi.y, aHi.z, aHi.w};
#pragma unroll
            for (int u = 0; u < 8; u++) {
                unsigned long long aa = pack_dup(a[u]);
                ffma2(acc2[u][0], aa, w0);
                ffma2(acc2[u][1], aa, w1);
                ffma2(acc2[u][2], aa, w2);
                ffma2(acc2[u][3], aa, w3);
            }
        }
    }

    float bv[8];
#pragma unroll
    for (int v = 0; v < 4; v++) {
        bv[v]     = bias[tx * 4 + v];
        bv[v + 4] = bias[tx * 4 + 64 + v];
    }

#pragma unroll
    for (int u = 0; u < 8; u++) {
        int gr = brow + ((u < 4) ? (ty * 4 + u) : (ty * 4 + 64 + u - 4));
        if (gr >= N) continue;
        float* o = out + (size_t)gr * 256 + 128;
        float2 p0 = unpack2(acc2[u][0]);
        float2 p1 = unpack2(acc2[u][1]);
        float2 p2 = unpack2(acc2[u][2]);
        float2 p3 = unpack2(acc2[u][3]);
        float y[8] = {p0.x, p0.y, p1.x, p1.y, p2.x, p2.y, p3.x, p3.y};
#pragma unroll
        for (int v = 0; v < 8; v++) {
            float z = y[v] + bv[v];
            y[v] = (z >= 0.0f) ? z : 0.2f * z;
        }
        *reinterpret_cast<float4*>(o + tx * 4)      = make_float4(y[0], y[1], y[2], y[3]);
        *reinterpret_cast<float4*>(o + tx * 4 + 64) = make_float4(y[4], y[5], y[6], y[7]);
    }
}

// ---------------------------------------------------------------------------
extern "C" void kernel_launch(void* const* d_in, const int* in_sizes, int n_in,
                              void* d_out, int out_size) {
    const int*   x       = (const int*)d_in[0];
    const int*   row     = (const int*)d_in[1];
    const int*   col     = (const int*)d_in[2];
    const float* vals    = (const float*)d_in[3];
    const float* embed_w = (const float*)d_in[4];
    const float* fc_w    = (const float*)d_in[5];
    const float* fc_b    = (const float*)d_in[6];
    float* out = (float*)d_out;

    const int N = in_sizes[0];
    const int E = in_sizes[1];
    const int nchunks = (N + SCAN_CHUNK - 1) / SCAN_CHUNK;

    zero_counts_kernel<<<(N + 255) / 256, 256>>>(N);
    hist_kernel<<<((E + 3) / 4 + 255) / 256, 256>>>(row, E);
    scan_reduce_kernel<<<nchunks, 1024>>>(N);
    scan_sums_kernel<<<1, 32>>>(nchunks);
    scan_final_kernel<<<nchunks, 1024>>>(N, E);
    scatter_kernel<<<(E + 255) / 256, 256>>>(row, col, vals, x, E);

    spmm_csr_kernel<<<(N * 32 + 255) / 256, 256>>>(x, embed_w, out, N);

    gemm_kernel<<<(N + 127) / 128, 256>>>(fc_w, fc_b, out, N);
}